// round 17
// baseline (speedup 1.0000x reference)
#include <cuda_runtime.h>
#include <cuda_fp16.h>
#include <math.h>
#include <stdint.h>

// ---------------------------------------------------------------------------
// Problem constants
// ---------------------------------------------------------------------------
#define NTOK  16384
#define DIN   2048
#define HMID  4096
#define NEXP  64
#define NSHARED 8
#define TOPK  2

// Output layout (flattened concat of the reference tuple)
#define G_OFF  0
#define LW_OFF (NTOK * NSHARED)
#define LI_OFF (LW_OFF + NTOK * TOPK)
#define W_OFF  (LI_OFF + NTOK * TOPK)

// ---------------------------------------------------------------------------
// Scratch (static device arrays; no allocation)
// ---------------------------------------------------------------------------
__device__ __half g_x0[(size_t)NTOK * DIN];           // x limb planes
__device__ __half g_x1[(size_t)NTOK * DIN];
__device__ __half g_w0[(size_t)HMID * DIN];           // W1^T limb planes
__device__ __half g_w1[(size_t)HMID * DIN];
__device__ __half g_u0[(size_t)NEXP * HMID];          // W2^T limb planes
__device__ __half g_u1[(size_t)NEXP * HMID];
__device__ float  g_logits[NTOK][NEXP];               // fused router logits
__device__ unsigned int g_cnt[NTOK / 128];            // row-tile completion

__device__ __forceinline__ uint32_t smem_u32(const void* p) {
    uint32_t a;
    asm("{ .reg .u64 t; cvta.to.shared.u64 t, %1; cvt.u32.u64 %0, t; }"
        : "=r"(a) : "l"(p));
    return a;
}

__device__ __forceinline__ float gelu_exact(float v) {
    return 0.5f * v * (1.0f + erff(v * 0.70710678118654752440f));
}

__device__ __forceinline__ void ldsm_x4(uint32_t* r, uint32_t addr) {
    asm volatile("ldmatrix.sync.aligned.m8n8.x4.shared.b16 {%0,%1,%2,%3}, [%4];"
                 : "=r"(r[0]), "=r"(r[1]), "=r"(r[2]), "=r"(r[3]) : "r"(addr));
}

__device__ __forceinline__ void mma16816(float* d, const uint32_t* a,
                                         uint32_t b0, uint32_t b1) {
    asm volatile(
        "mma.sync.aligned.m16n8k16.row.col.f32.f16.f16.f32 "
        "{%0,%1,%2,%3}, {%4,%5,%6,%7}, {%8,%9}, {%0,%1,%2,%3};"
        : "+f"(d[0]), "+f"(d[1]), "+f"(d[2]), "+f"(d[3])
        : "r"(a[0]), "r"(a[1]), "r"(a[2]), "r"(a[3]), "r"(b0), "r"(b1));
}

#define CP_ASYNC16(dst, src) \
    asm volatile("cp.async.cg.shared.global [%0], [%1], 16;" \
                 :: "r"(dst), "l"(src) : "memory")
#define CP_COMMIT() asm volatile("cp.async.commit_group;" ::: "memory")
#define BAR_SYNC(id, cnt) \
    asm volatile("bar.sync %0, %1;" :: "r"(id), "r"(cnt) : "memory")
#define BAR_ARRIVE(id, cnt) \
    asm volatile("bar.arrive %0, %1;" :: "r"(id), "r"(cnt) : "memory")

__device__ __forceinline__ uint32_t pack_limbs(float x, float y,
                                               float& rx, float& ry) {
    __half hx = __float2half_rn(x), hy = __float2half_rn(y);
    rx = x - __half2float(hx);
    ry = y - __half2float(hy);
    return (uint32_t)__half_as_ushort(hx) | ((uint32_t)__half_as_ushort(hy) << 16);
}

// ---------------------------------------------------------------------------
// prep: one kernel, block-range dispatch.
//   [0, NXB)                 : x -> fp16 limb planes (8 elems/thread)
//   [NXB, NXB+NW1B)          : W1 transpose+split (32x32 tiles)
//   [.., +NW2B)              : W2 transpose+split
//   [.., +NZB)               : zero g_logits (+ g_cnt in first zero block)
// ---------------------------------------------------------------------------
#define NXB  ((NTOK * DIN) / (256 * 8))               // 16384
#define NW1B ((HMID / 32) * (DIN / 32))               // 8192
#define NW2B ((NEXP / 32) * (HMID / 32))              // 256
#define NZB  ((NTOK * NEXP) / (256 * 4))              // 1024

__global__ void __launch_bounds__(256)
prep_kernel(const float* __restrict__ x,
            const float* __restrict__ W1,
            const float* __restrict__ W2) {
    __shared__ float tile[32][33];
    const int b = blockIdx.x;
    const int tid = threadIdx.x;

    if (b < NXB) {
        size_t i = ((size_t)b * 256 + tid) * 8;
#pragma unroll
        for (int half = 0; half < 2; half++) {
            size_t ii = i + half * 4;
            float4 v = *reinterpret_cast<const float4*>(&x[ii]);
            float a[4] = {v.x, v.y, v.z, v.w};
            unsigned short u0[4], u1[4];
#pragma unroll
            for (int j = 0; j < 4; j++) {
                __half h0 = __float2half_rn(a[j]);
                float r = a[j] - __half2float(h0);
                u0[j] = __half_as_ushort(h0);
                u1[j] = __half_as_ushort(__float2half_rn(r));
            }
            *reinterpret_cast<uint2*>(&g_x0[ii]) =
                make_uint2((uint32_t)u0[0] | ((uint32_t)u0[1] << 16),
                           (uint32_t)u0[2] | ((uint32_t)u0[3] << 16));
            *reinterpret_cast<uint2*>(&g_x1[ii]) =
                make_uint2((uint32_t)u1[0] | ((uint32_t)u1[1] << 16),
                           (uint32_t)u1[2] | ((uint32_t)u1[3] << 16));
        }
        return;
    }
    if (b < NXB + NW1B) {
        const int r = b - NXB;
        const int n0 = (r & 127) * 32;          // HMID/32 = 128
        const int k0 = (r >> 7) * 32;
        const int tx = tid & 31, ty = tid >> 5;
#pragma unroll
        for (int j = 0; j < 4; j++)
            tile[ty + j * 8][tx] = W1[(size_t)(k0 + ty + j * 8) * HMID + n0 + tx];
        __syncthreads();
#pragma unroll
        for (int j = 0; j < 4; j++) {
            float v = tile[tx][ty + j * 8];
            __half h0 = __float2half_rn(v);
            float rr = v - __half2float(h0);
            size_t o = (size_t)(n0 + ty + j * 8) * DIN + k0 + tx;
            g_w0[o] = h0;
            g_w1[o] = __float2half_rn(rr);
        }
        return;
    }
    if (b < NXB + NW1B + NW2B) {
        const int r = b - NXB - NW1B;
        const int n0 = (r & 1) * 32;            // NEXP/32 = 2
        const int k0 = (r >> 1) * 32;
        const int tx = tid & 31, ty = tid >> 5;
#pragma unroll
        for (int j = 0; j < 4; j++)
            tile[ty + j * 8][tx] = W2[(size_t)(k0 + ty + j * 8) * NEXP + n0 + tx];
        __syncthreads();
#pragma unroll
        for (int j = 0; j < 4; j++) {
            float v = tile[tx][ty + j * 8];
            __half h0 = __float2half_rn(v);
            float rr = v - __half2float(h0);
            size_t o = (size_t)(n0 + ty + j * 8) * HMID + k0 + tx;
            g_u0[o] = h0;
            g_u1[o] = __float2half_rn(rr);
        }
        return;
    }
    {
        const int r = b - NXB - NW1B - NW2B;
        size_t i = ((size_t)r * 256 + tid) * 4;
        *reinterpret_cast<float4*>(&g_logits[0][0] + i) =
            make_float4(0.f, 0.f, 0.f, 0.f);
        if (r == 0 && tid < NTOK / 128) g_cnt[tid] = 0u;
    }
}

// ---------------------------------------------------------------------------
// gemm1 + fused router partial + last-CTA finalize:
//   mainloop: h = x @ W1 (fp16 2-limb, 3 products), named-barrier pipeline
//   epilogue: bias+gelu -> h limbs in smem; W2^T K-slice; 3-product HMMA
//             128 tok x 64 exp x K=128; atomicAdd into g_logits.
//   tail:     last col-tile CTA per row-tile (via g_cnt) runs softmax/top-2
//             and writes all outputs for its 128 tokens.
// ---------------------------------------------------------------------------
#define TILE64  (128 * 64)
#define STAGE64 (4 * TILE64)
#define GSTAGES 3
#define SMEM_GEMM (GSTAGES * STAGE64)  // 98304
#define KT (DIN / 32)                  // 64
#define H0_OFF 0
#define H1_OFF 32768
#define U0_OFF 65536
#define U1_OFF 81920
#define LGS 68

__global__ void __launch_bounds__(256, 2)
gemm1_hmma_kernel(const float* __restrict__ b1,
                  const float* __restrict__ b2,
                  float* __restrict__ out) {
    extern __shared__ char smem[];
    __shared__ unsigned int sIsLast;
    const uint32_t sbase = smem_u32(smem);
    const int tid = threadIdx.x;
    const int wid = tid >> 5;
    const int lid = tid & 31;
    const int row0 = blockIdx.y * 128;
    const int col0 = blockIdx.x * 128;
    const int wm = (wid >> 2) * 64;
    const int wn = (wid & 3) * 32;

    const int lr = tid >> 1;
    const int cc = (tid & 1) * 2;
    const int mS = (lr >> 1) & 3;
    const uint32_t dst0 = (uint32_t)lr * 64 + (uint32_t)(((cc)     ^ mS) << 4);
    const uint32_t dst1 = (uint32_t)lr * 64 + (uint32_t)(((cc + 1) ^ mS) << 4);
    const char* gA0 = (const char*)(g_x0 + (size_t)(row0 + lr) * DIN) + cc * 16;
    const char* gA1 = (const char*)(g_x1 + (size_t)(row0 + lr) * DIN) + cc * 16;
    const char* gB0 = (const char*)(g_w0 + (size_t)(col0 + lr) * DIN) + cc * 16;
    const char* gB1 = (const char*)(g_w1 + (size_t)(col0 + lr) * DIN) + cc * 16;

    float acc[4][4][4];
#pragma unroll
    for (int i = 0; i < 4; i++)
#pragma unroll
        for (int j = 0; j < 4; j++)
#pragma unroll
            for (int k = 0; k < 4; k++) acc[i][j][k] = 0.f;

    auto load_stage = [&](int s, int kt) {
        const uint32_t sb = sbase + s * STAGE64;
        const int go = kt * 64;
        CP_ASYNC16(sb + dst0,              gA0 + go);
        CP_ASYNC16(sb + dst1,              gA0 + go + 16);
        CP_ASYNC16(sb + TILE64 + dst0,     gA1 + go);
        CP_ASYNC16(sb + TILE64 + dst1,     gA1 + go + 16);
        CP_ASYNC16(sb + 2 * TILE64 + dst0, gB0 + go);
        CP_ASYNC16(sb + 2 * TILE64 + dst1, gB0 + go + 16);
        CP_ASYNC16(sb + 3 * TILE64 + dst0, gB1 + go);
        CP_ASYNC16(sb + 3 * TILE64 + dst1, gB1 + go + 16);
        CP_COMMIT();
    };

    const uint32_t aRowB = (uint32_t)(wm + (lid & 15)) * 64;
    const int cidxA = lid >> 4;
    const int mA = ((lid & 15) >> 1) & 3;
    const int brow = (lid & 7) + ((lid >> 4) & 1) * 8;
    const uint32_t bRowB = (uint32_t)(wn + brow) * 64;
    const int cidxB = (lid >> 3) & 1;
    const int mB = (brow >> 1) & 3;
    uint32_t aCol[2], bCol[2];
#pragma unroll
    for (int k16 = 0; k16 < 2; k16++) {
        aCol[k16] = (uint32_t)((((k16 << 1) | cidxA) ^ mA) << 4);
        bCol[k16] = (uint32_t)((((k16 << 1) | cidxB) ^ mB) << 4);
    }

    load_stage(0, 0);
    load_stage(1, 1);
    asm volatile("cp.async.wait_group 1;" ::: "memory");
    BAR_ARRIVE(1 + 0, 512);

    int r0 = 0, r1 = 1, r2 = 2;

    for (int kt = 0; kt < KT; kt++) {
        BAR_SYNC(1 + r0, 512);

        const uint32_t sb = sbase + r0 * STAGE64;

        // ================= k16 = 0 =================
        {
            uint32_t b0[2][4], b1f[2][4];
#pragma unroll
            for (int nt2 = 0; nt2 < 2; nt2++) {
                const uint32_t bo = bRowB + nt2 * 1024 + bCol[0];
                ldsm_x4(b0[nt2],  sb + 2 * TILE64 + bo);
                ldsm_x4(b1f[nt2], sb + 3 * TILE64 + bo);
            }
            uint32_t a0[4][4], a1[4][4];
#pragma unroll
            for (int mt = 0; mt < 4; mt++)
                ldsm_x4(a0[mt], sb + aRowB + mt * 1024 + aCol[0]);
#pragma unroll
            for (int mt = 0; mt < 4; mt++)
                ldsm_x4(a1[mt], sb + TILE64 + aRowB + mt * 1024 + aCol[0]);

#pragma unroll
            for (int mt = 0; mt < 4; mt++)
#pragma unroll
                for (int nt = 0; nt < 4; nt++) {
                    const int n2 = nt >> 1, h = (nt & 1) * 2;
                    mma16816(acc[mt][nt], a0[mt], b0[n2][h], b0[n2][h + 1]);
                }
#pragma unroll
            for (int mt = 0; mt < 4; mt++)
#pragma unroll
                for (int nt = 0; nt < 4; nt++) {
                    const int n2 = nt >> 1, h = (nt & 1) * 2;
                    mma16816(acc[mt][nt], a0[mt], b1f[n2][h], b1f[n2][h + 1]);
                }
#pragma unroll
            for (int mt = 0; mt < 4; mt++)
#pragma unroll
                for (int nt = 0; nt < 4; nt++) {
                    const int n2 = nt >> 1, h = (nt & 1) * 2;
                    mma16816(acc[mt][nt], a1[mt], b0[n2][h], b0[n2][h + 1]);
                }
        }

        // ================= k16 = 1 =================
        {
            uint32_t b0[2][4], b1f[2][4];
#pragma unroll
            for (int nt2 = 0; nt2 < 2; nt2++) {
                const uint32_t bo = bRowB + nt2 * 1024 + bCol[1];
                ldsm_x4(b0[nt2],  sb + 2 * TILE64 + bo);
                ldsm_x4(b1f[nt2], sb + 3 * TILE64 + bo);
            }
            uint32_t a0[4][4], a1[4][4];
#pragma unroll
            for (int mt = 0; mt < 4; mt++)
                ldsm_x4(a0[mt], sb + aRowB + mt * 1024 + aCol[1]);
#pragma unroll
            for (int mt = 0; mt < 4; mt++)
                ldsm_x4(a1[mt], sb + TILE64 + aRowB + mt * 1024 + aCol[1]);

            if (kt + 3 < KT) BAR_ARRIVE(4 + r0, 512);
            if (kt >= 1 && kt + 2 < KT) BAR_SYNC(4 + r2, 512);
            if (kt + 2 < KT) load_stage(r2, kt + 2);

#pragma unroll
            for (int mt = 0; mt < 4; mt++)
#pragma unroll
                for (int nt = 0; nt < 4; nt++) {
                    const int n2 = nt >> 1, h = (nt & 1) * 2;
                    mma16816(acc[mt][nt], a0[mt], b0[n2][h], b0[n2][h + 1]);
                }

            if (kt + 1 < KT) {
                if (kt + 2 < KT) {
                    asm volatile("cp.async.wait_group 1;" ::: "memory");
                } else {
                    asm volatile("cp.async.wait_group 0;" ::: "memory");
                }
                BAR_ARRIVE(1 + r1, 512);
            }

#pragma unroll
            for (int mt = 0; mt < 4; mt++)
#pragma unroll
                for (int nt = 0; nt < 4; nt++) {
                    const int n2 = nt >> 1, h = (nt & 1) * 2;
                    mma16816(acc[mt][nt], a0[mt], b1f[n2][h], b1f[n2][h + 1]);
                }
#pragma unroll
            for (int mt = 0; mt < 4; mt++)
#pragma unroll
                for (int nt = 0; nt < 4; nt++) {
                    const int n2 = nt >> 1, h = (nt & 1) * 2;
                    mma16816(acc[mt][nt], a1[mt], b0[n2][h], b0[n2][h + 1]);
                }
        }

        const int t = r0; r0 = r1; r1 = r2; r2 = t;
    }

    // =========================== fused epilogue ===========================
    __syncthreads();

    {
        const int ue = tid >> 2;
        const int c0 = (tid & 3) * 4;
        const char* gu0 = (const char*)(g_u0 + (size_t)ue * HMID + col0);
        const char* gu1 = (const char*)(g_u1 + (size_t)ue * HMID + col0);
#pragma unroll
        for (int c = 0; c < 4; c++) {
            int ch = c0 + c;
            uint32_t d = (uint32_t)ue * 256 + (uint32_t)((ch ^ (ue & 15)) << 4);
            CP_ASYNC16(sbase + U0_OFF + d, gu0 + ch * 16);
            CP_ASYNC16(sbase + U1_OFF + d, gu1 + ch * 16);
        }
        CP_COMMIT();
    }

    const int g = lid >> 2;
    const int i2 = (lid & 3) * 2;
#pragma unroll
    for (int nt = 0; nt < 4; nt++) {
        const int col = wn + nt * 8 + i2;
        const float bx = b1[col0 + col], by = b1[col0 + col + 1];
        const uint32_t chunkOff = (uint32_t)((col & 7) * 2);
        const uint32_t chunkIdx = (uint32_t)(col >> 3);
#pragma unroll
        for (int mt = 0; mt < 4; mt++) {
            const int rowL = wm + mt * 16 + g;
            const int rowH = rowL + 8;
            float lox = gelu_exact(acc[mt][nt][0] + bx);
            float loy = gelu_exact(acc[mt][nt][1] + by);
            float hix = gelu_exact(acc[mt][nt][2] + bx);
            float hiy = gelu_exact(acc[mt][nt][3] + by);
            float r0f, r1f, r2f, r3f;
            uint32_t p0 = pack_limbs(lox, loy, r0f, r1f);
            uint32_t p1 = pack_limbs(hix, hiy, r2f, r3f);
            uint32_t q0 = (uint32_t)__half_as_ushort(__float2half_rn(r0f)) |
                          ((uint32_t)__half_as_ushort(__float2half_rn(r1f)) << 16);
            uint32_t q1 = (uint32_t)__half_as_ushort(__float2half_rn(r2f)) |
                          ((uint32_t)__half_as_ushort(__float2half_rn(r3f)) << 16);
            uint32_t stL = (uint32_t)rowL * 256 +
                           ((chunkIdx ^ (uint32_t)(rowL & 15)) << 4) + chunkOff;
            uint32_t stH = (uint32_t)rowH * 256 +
                           ((chunkIdx ^ (uint32_t)(rowH & 15)) << 4) + chunkOff;
            *reinterpret_cast<uint32_t*>(smem + H0_OFF + stL) = p0;
            *reinterpret_cast<uint32_t*>(smem + H0_OFF + stH) = p1;
            *reinterpret_cast<uint32_t*>(smem + H1_OFF + stL) = q0;
            *reinterpret_cast<uint32_t*>(smem + H1_OFF + stH) = q1;
        }
    }
    asm volatile("cp.async.wait_group 0;" ::: "memory");
    __syncthreads();

    const int wmF = (wid >> 1) * 32;
    const int wnF = (wid & 1) * 32;
    const int aRowM = lid & 15;
    float accF[2][4][4];
#pragma unroll
    for (int i = 0; i < 2; i++)
#pragma unroll
        for (int j = 0; j < 4; j++)
#pragma unroll
            for (int k = 0; k < 4; k++) accF[i][j][k] = 0.f;

#pragma unroll
    for (int k16 = 0; k16 < 8; k16++) {
        uint32_t b0[2][4], b1f[2][4];
#pragma unroll
        for (int nt2 = 0; nt2 < 2; nt2++) {
            const uint32_t rb = (uint32_t)(wnF + nt2 * 16 + brow) * 256 +
                                (uint32_t)(((k16 * 2 + cidxB) ^ brow) << 4);
            ldsm_x4(b0[nt2],  sbase + U0_OFF + rb);
            ldsm_x4(b1f[nt2], sbase + U1_OFF + rb);
        }
        uint32_t a0[2][4], a1[2][4];
#pragma unroll
        for (int mt = 0; mt < 2; mt++) {
            const uint32_t ra = (uint32_t)(wmF + mt * 16 + aRowM) * 256 +
                                (uint32_t)(((k16 * 2 + cidxA) ^ aRowM) << 4);
            ldsm_x4(a0[mt], sbase + H0_OFF + ra);
            ldsm_x4(a1[mt], sbase + H1_OFF + ra);
        }
#pragma unroll
        for (int mt = 0; mt < 2; mt++)
#pragma unroll
            for (int nt = 0; nt < 4; nt++) {
                const int n2 = nt >> 1, h = (nt & 1) * 2;
                mma16816(accF[mt][nt], a0[mt], b0[n2][h], b0[n2][h + 1]);
            }
#pragma unroll
        for (int mt = 0; mt < 2; mt++)
#pragma unroll
            for (int nt = 0; nt < 4; nt++) {
                const int n2 = nt >> 1, h = (nt & 1) * 2;
                mma16816(accF[mt][nt], a0[mt], b1f[n2][h], b1f[n2][h + 1]);
            }
#pragma unroll
        for (int mt = 0; mt < 2; mt++)
#pragma unroll
            for (int nt = 0; nt < 4; nt++) {
                const int n2 = nt >> 1, h = (nt & 1) * 2;
                mma16816(accF[mt][nt], a1[mt], b0[n2][h], b0[n2][h + 1]);
            }
    }

#pragma unroll
    for (int nt = 0; nt < 4; nt++) {
        const int ce = wnF + nt * 8 + i2;
#pragma unroll
        for (int mt = 0; mt < 2; mt++) {
            const int rt = row0 + wmF + mt * 16 + g;
            atomicAdd(&g_logits[rt][ce],         accF[mt][nt][0]);
            atomicAdd(&g_logits[rt][ce + 1],     accF[mt][nt][1]);
            atomicAdd(&g_logits[rt + 8][ce],     accF[mt][nt][2]);
            atomicAdd(&g_logits[rt + 8][ce + 1], accF[mt][nt][3]);
        }
    }

    // ================= last-CTA-per-row-tile finalize =================
    __threadfence();
    __syncthreads();
    if (tid == 0)
        sIsLast = (atomicAdd(&g_cnt[blockIdx.y], 1u) == (HMID / 128) - 1u);
    __syncthreads();
    if (!sIsLast) return;
    __threadfence();   // acquire: observe all row-tile atomics

    float* lg   = reinterpret_cast<float*>(smem);
    float* sinv = lg + 128 * LGS;

#pragma unroll
    for (int hh = 0; hh < 8; hh++) {
        int f = tid + 256 * hh;
        int row = f >> 4;
        int c4 = (f & 15) * 4;
        float4 s = *reinterpret_cast<const float4*>(&g_logits[row0 + row][c4]);
        float4 bb = *reinterpret_cast<const float4*>(&b2[c4]);
        s.x += bb.x; s.y += bb.y; s.z += bb.z; s.w += bb.w;
        *reinterpret_cast<float4*>(&lg[row * LGS + c4]) = s;
    }
    __syncthreads();

    if (tid < 128) {
        const int tok = row0 + tid;
        float* row = &lg[tid * LGS];
        float mx = -1e30f;
#pragma unroll
        for (int e = 0; e < NEXP; e++) mx = fmaxf(mx, row[e]);
        float s = 0.f;
#pragma unroll
        for (int e = 0; e < NEXP; e++) {
            float ev = expf(row[e] - mx);
            row[e] = ev;
            s += ev;
        }
        float inv = 1.0f / s;
        sinv[tid] = inv;

        float v1 = -1.0f, v2 = -1.0f;
        int i1 = 0, i2v = 0;
#pragma unroll
        for (int e = NSHARED; e < NEXP; e++) {
            float v = row[e];
            if (v > v1)      { v2 = v1; i2v = i1; v1 = v; i1 = e; }
            else if (v > v2) { v2 = v;  i2v = e; }
        }
#pragma unroll
        for (int e = 0; e < NSHARED; e++)
            out[G_OFF + (size_t)tok * NSHARED + e] = row[e] * inv;
        out[LW_OFF + (size_t)tok * TOPK + 0] = v1 * inv;
        out[LW_OFF + (size_t)tok * TOPK + 1] = v2 * inv;
        out[LI_OFF + (size_t)tok * TOPK + 0] = (float)(i1 - NSHARED);
        out[LI_OFF + (size_t)tok * TOPK + 1] = (float)(i2v - NSHARED);
    }
    __syncthreads();

#pragma unroll
    for (int hh = 0; hh < 16; hh++) {
        int f = tid + 256 * hh;
        int tr = f >> 5;
        int ec = (f & 31) * 2;
        float inv = sinv[tr];
        float2 v = *reinterpret_cast<const float2*>(&lg[tr * LGS + ec]);
        v.x *= inv; v.y *= inv;
        *reinterpret_cast<float2*>(
            &out[W_OFF + (size_t)(row0 + tr) * NEXP + ec]) = v;
    }
}

// ---------------------------------------------------------------------------
extern "C" void kernel_launch(void* const* d_in, const int* in_sizes, int n_in,
                              void* d_out, int out_size) {
    const float* x  = (const float*)d_in[0];
    const float* W1 = (const float*)d_in[1];
    const float* b1 = (const float*)d_in[2];
    const float* W2 = (const float*)d_in[3];
    const float* b2 = (const float*)d_in[4];
    float* out = (float*)d_out;

    static int attr_done = 0;
    if (!attr_done) {
        cudaFuncSetAttribute(gemm1_hmma_kernel,
                             cudaFuncAttributeMaxDynamicSharedMemorySize, SMEM_GEMM);
        attr_done = 1;
    }

    prep_kernel<<<NXB + NW1B + NW2B + NZB, 256>>>(x, W1, W2);
    gemm1_hmma_kernel<<<dim3(HMID / 128, NTOK / 128), 256, SMEM_GEMM>>>(b1, b2, out);
}